// round 12
// baseline (speedup 1.0000x reference)
#include <cuda_runtime.h>
#include <cuda_bf16.h>
#include <cstdint>

#define N_NODES 4096
#define HIDDEN  64
#define N_REL   8
#define N_LAYERS 2
#define NH (N_NODES * HIDDEN)

// ---------------------------------------------------------------- helpers
__device__ __forceinline__ uint32_t smem_u32(const void* p) {
    uint32_t a;
    asm("{ .reg .u64 t; cvta.to.shared.u64 t, %1; cvt.u32.u64 %0, t; }" : "=r"(a) : "l"(p));
    return a;
}

// pack two floats into bf16x2 (f_even -> low half)
#define CVT_BF16X2(d, f_even, f_odd) \
    asm("cvt.rn.bf16x2.f32 %0, %1, %2;" : "=r"(d) : "f"(f_odd), "f"(f_even))

#define LDSM4(r, addr) \
    asm volatile("ldmatrix.sync.aligned.m8n8.x4.shared.b16 {%0,%1,%2,%3}, [%4];" \
        : "=r"((r)[0]), "=r"((r)[1]), "=r"((r)[2]), "=r"((r)[3]) : "r"(addr))

#define LDS64F(e, o, addr) \
    asm volatile("ld.shared.v2.f32 {%0,%1}, [%2];" : "=f"(e), "=f"(o) : "r"(addr))

#define MMA16816(c, a, b0, b1) \
    asm volatile("mma.sync.aligned.m16n8k16.row.col.f32.bf16.bf16.f32 " \
        "{%0,%1,%2,%3}, {%4,%5,%6,%7}, {%8,%9}, {%0,%1,%2,%3};" \
        : "+f"((c)[0]), "+f"((c)[1]), "+f"((c)[2]), "+f"((c)[3]) \
        : "r"((a)[0]), "r"((a)[1]), "r"((a)[2]), "r"((a)[3]), "r"(b0), "r"(b1))

#define LDGSTS16(dst, src) \
    asm volatile("cp.async.cg.shared.global [%0], [%1], 16;" :: "r"(dst), "l"(src))
#define CP_COMMIT() asm volatile("cp.async.commit_group;" ::: "memory")
#define CP_WAIT1() asm volatile("cp.async.wait_group 1;" ::: "memory")
#define CP_WAIT0() asm volatile("cp.async.wait_group 0;" ::: "memory")

// ---------------------------------------------------------------- scratch
__device__ float g_h[2][NH];                              // g_h[l] = output of layer l
__device__ float g_S[NH];
__device__ float g_part[N_REL][NH];
__device__ __nv_bfloat16 g_Yth[N_REL][HIDDEN][N_NODES];   // Y^T hi  [r][e][m]
__device__ __nv_bfloat16 g_Ytl[N_REL][HIDDEN][N_NODES];   // Y^T lo

// ---------------------------------------------------------------- Y / S
__global__ void __launch_bounds__(256) compute_ys_kernel(
    const float* __restrict__ h,
    const float* __restrict__ w_self,
    const float* __restrict__ w_rel,
    int layer,
    __nv_bfloat16* __restrict__ Yth,
    __nv_bfloat16* __restrict__ Ytl,
    float* __restrict__ S)
{
    __shared__ float sbuf[8448];
    float* Ws = sbuf;
    float* Hs = sbuf + 4096;
    float* Os = sbuf + 4096;

    int m0 = blockIdx.x * 64;
    int wi = blockIdx.y;
    const float* W = (wi < N_REL)
        ? (w_rel + ((size_t)layer * N_REL + wi) * HIDDEN * HIDDEN)
        : (w_self + (size_t)layer * HIDDEN * HIDDEN);

    int tid = threadIdx.x;
    const float4* Wg = (const float4*)W;
    const float4* Hg = (const float4*)(h + (size_t)m0 * HIDDEN);
    for (int i = tid; i < 1024; i += 256) {
        ((float4*)Ws)[i] = Wg[i];
        ((float4*)Hs)[i] = Hg[i];
    }
    __syncthreads();

    int tx = tid & 15, ty = tid >> 4;
    int e0 = tx * 4;
    float4 acc[4];
    #pragma unroll
    for (int mi = 0; mi < 4; mi++) {
        int m = ty * 4 + mi;
        float4 a = make_float4(0.f, 0.f, 0.f, 0.f);
        #pragma unroll
        for (int d = 0; d < HIDDEN; d++) {
            float hv = Hs[m * HIDDEN + d];
            float4 wv = *(const float4*)&Ws[d * HIDDEN + e0];
            a.x = fmaf(hv, wv.x, a.x);
            a.y = fmaf(hv, wv.y, a.y);
            a.z = fmaf(hv, wv.z, a.z);
            a.w = fmaf(hv, wv.w, a.w);
        }
        acc[mi] = a;
    }

    if (wi == N_REL) {
        #pragma unroll
        for (int mi = 0; mi < 4; mi++)
            *(float4*)&S[(size_t)(m0 + ty * 4 + mi) * HIDDEN + e0] = acc[mi];
        return;
    }

    __syncthreads();
    #pragma unroll
    for (int mi = 0; mi < 4; mi++)
        *(float4*)&Os[(ty * 4 + mi) * 68 + e0] = acc[mi];
    __syncthreads();

    int e   = tid >> 2;
    int seg = tid & 3;
    float v[16];
    #pragma unroll
    for (int i = 0; i < 16; i++)
        v[i] = Os[(seg * 16 + i) * 68 + e];

    uint32_t hw[8], lw[8];
    #pragma unroll
    for (int j = 0; j < 8; j++) {
        CVT_BF16X2(hw[j], v[2 * j], v[2 * j + 1]);
        float re = v[2 * j]     - __uint_as_float(hw[j] << 16);
        float ro = v[2 * j + 1] - __uint_as_float(hw[j] & 0xffff0000u);
        CVT_BF16X2(lw[j], re, ro);
    }
    size_t off = ((size_t)wi * HIDDEN + e) * N_NODES + m0 + seg * 16;
    *(uint4*)(Yth + off)     = make_uint4(hw[0], hw[1], hw[2], hw[3]);
    *(uint4*)(Yth + off + 8) = make_uint4(hw[4], hw[5], hw[6], hw[7]);
    *(uint4*)(Ytl + off)     = make_uint4(lw[0], lw[1], lw[2], lw[3]);
    *(uint4*)(Ytl + off + 8) = make_uint4(lw[4], lw[5], lw[6], lw[7]);
}

// ---------------------------------------------------------------- pipelined tensor GEMM
// CTA 128(M) x 64(N), 4 warps, warp tile 32x64, KC=32, 2-stage cp.async,
// 3 CTAs/SM (stage 30720 B). A fp32 rows stride 160B (40 words == 8 mod 32:
// LDS.64 phases tile banks perfectly, no XOR). B bf16 limbs rows 64B padded
// to 80B (20 words: 8-row LDSM groups hit distinct bank-quads, no XOR).
#define KC 32
#define A_STRIDE 160
#define B_STRIDE 80
#define BH_OFF 20480
#define BL_OFF 25600
#define STAGE_BYTES 30720

__device__ __forceinline__ void load_stage(
    uint32_t sbase, int stage, int mt, int tid,
    const float* Ag,
    const __nv_bfloat16* Bhg, const __nv_bfloat16* Blg)
{
    const uint32_t st = sbase + stage * STAGE_BYTES;
    // A: 128 rows x 32 fp32 = 1024 16B-chunks; 8 per thread
    #pragma unroll
    for (int i = 0; i < 8; i++) {
        int c = tid + i * 128;
        int row = c >> 3, ch = c & 7;
        uint32_t dst = st + row * A_STRIDE + ch * 16;
        const float* src = Ag + (size_t)row * N_NODES + mt + ch * 4;
        LDGSTS16(dst, src);
    }
    // B: 64 rows x 32 bf16 (64B data, 80B stride) per limb = 256 chunks each
    // lane->row mapping keeps STS conflict-free; gmem side is L2-served.
    #pragma unroll
    for (int i = 0; i < 2; i++) {
        int c = tid + i * 128;
        int row = c & 63, ch = c >> 6;   // ch in 0..3
        uint32_t dst = st + row * B_STRIDE + ch * 16;
        size_t src = (size_t)row * N_NODES + mt + ch * 8;
        LDGSTS16(dst + BH_OFF, Bhg + src);
        LDGSTS16(dst + BL_OFF, Blg + src);
    }
}

__global__ void __launch_bounds__(128, 3) gemm_pipe_kernel(
    const float* __restrict__ adj,
    const __nv_bfloat16* __restrict__ Yth,
    const __nv_bfloat16* __restrict__ Ytl,
    float* __restrict__ part)
{
    extern __shared__ __align__(16) char smem[];
    const int tid  = threadIdx.x;
    const int lane = tid & 31;
    const int warp_m = tid >> 5;        // 4 m-groups of 32; warp covers all 64 N
    const int n0 = blockIdx.x * 128;
    const int r  = blockIdx.y;
    const uint32_t sbase = smem_u32(smem);

    const float* Ag = adj + ((size_t)r << 24) + (size_t)(n0) * N_NODES;
    const __nv_bfloat16* Bhg = Yth + (size_t)r * HIDDEN * N_NODES;
    const __nv_bfloat16* Blg = Ytl + (size_t)r * HIDDEN * N_NODES;

    const int a_g = lane >> 2;
    const int a_t2 = (lane & 3) * 2;
    const int b_row_l = (lane >> 4) * 8 + (lane & 7);
    const int b_csel  = (lane >> 3) & 1;

    float c[2][8][4];
    #pragma unroll
    for (int i = 0; i < 2; i++)
        #pragma unroll
        for (int j = 0; j < 8; j++)
            #pragma unroll
            for (int k = 0; k < 4; k++) c[i][j][k] = 0.f;

    load_stage(sbase, 0, 0, tid, Ag, Bhg, Blg);
    CP_COMMIT();

    #pragma unroll 1
    for (int it = 0; it < N_NODES / KC; ++it) {
        const int buf = it & 1;
        if (it < N_NODES / KC - 1) {
            load_stage(sbase, buf ^ 1, (it + 1) * KC, tid, Ag, Bhg, Blg);
            CP_COMMIT();
            CP_WAIT1();
        } else {
            CP_WAIT0();
        }
        __syncthreads();

        const uint32_t st = sbase + buf * STAGE_BYTES;
        #pragma unroll
        for (int ks = 0; ks < 2; ks++) {
            // ---- B fragments (hi & lo limbs), 4 quads cover all 64 N ----
            uint32_t bh[4][4], bl[4][4];
            #pragma unroll
            for (int p = 0; p < 4; p++) {
                int brow = p * 16 + b_row_l;
                uint32_t boff = brow * B_STRIDE + (ks * 2 + b_csel) * 16;
                LDSM4(bh[p], st + BH_OFF + boff);
                LDSM4(bl[p], st + BL_OFF + boff);
            }
            // ---- A fragments: LDS.64 fp32 pairs -> bf16 hi/lo split ----
            #pragma unroll
            for (int mi = 0; mi < 2; mi++) {
                uint32_t ah[4], al[4];
                #pragma unroll
                for (int j = 0; j < 4; j++) {
                    int row = warp_m * 32 + mi * 16 + a_g + (j & 1) * 8;
                    int k   = ks * 16 + ((j >> 1) << 3) + a_t2;
                    uint32_t addr = st + row * A_STRIDE + k * 4;
                    float e, o;
                    LDS64F(e, o, addr);
                    uint32_t hq;
                    CVT_BF16X2(hq, e, o);
                    ah[j] = hq;
                    float re = e - __uint_as_float(hq << 16);
                    float ro = o - __uint_as_float(hq & 0xffff0000u);
                    CVT_BF16X2(al[j], re, ro);
                }
                #pragma unroll
                for (int p = 0; p < 4; p++) {
                    #pragma unroll
                    for (int q = 0; q < 2; q++) {
                        const int nf = p * 2 + q;
                        MMA16816(c[mi][nf], ah, bh[p][q * 2], bh[p][q * 2 + 1]);
                        MMA16816(c[mi][nf], al, bh[p][q * 2], bh[p][q * 2 + 1]);
                        MMA16816(c[mi][nf], ah, bl[p][q * 2], bl[p][q * 2 + 1]);
                    }
                }
            }
        }
        __syncthreads();
    }

    // epilogue
    float* P = part + (size_t)r * NH;
    #pragma unroll
    for (int mi = 0; mi < 2; mi++) {
        const int rbase = n0 + warp_m * 32 + mi * 16 + (lane >> 2);
        #pragma unroll
        for (int nf = 0; nf < 8; nf++) {
            const int cbase = nf * 8 + (lane & 3) * 2;
            *(float2*)&P[(size_t)rbase * HIDDEN + cbase] =
                make_float2(c[mi][nf][0], c[mi][nf][1]);
            *(float2*)&P[(size_t)(rbase + 8) * HIDDEN + cbase] =
                make_float2(c[mi][nf][2], c[mi][nf][3]);
        }
    }
}

// ---------------------------------------------------------------- finish
__global__ void finish_kernel(const float* __restrict__ S,
                              const float* __restrict__ part,
                              float* __restrict__ hn)
{
    int i = blockIdx.x * blockDim.x + threadIdx.x;
    if (i < NH) {
        float v = S[i];
        #pragma unroll
        for (int r = 0; r < N_REL; r++) v += part[(size_t)r * NH + i];
        hn[i] = fmaxf(v, 0.f);
    }
}

// ---------------------------------------------------------------- gather
__global__ void gather_kernel(const float* __restrict__ h,
                              const int* __restrict__ ids,
                              float* __restrict__ out)
{
    int k = blockIdx.x;
    int e = threadIdx.x;
    int id = ids[k];
    float v = (id < N_NODES) ? h[(size_t)id * HIDDEN + e] : 0.f;
    out[(size_t)k * HIDDEN + e] = v;
}

// ----------------------------------------------------------------
extern "C" void kernel_launch(void* const* d_in, const int* in_sizes, int n_in,
                              void* d_out, int out_size)
{
    const float* node_embed  = (const float*)d_in[0];
    const float* w_self      = (const float*)d_in[1];
    const float* w_rel       = (const float*)d_in[2];
    const float* rel_adj     = (const float*)d_in[3];
    const int*   keyword_ids = (const int*)d_in[4];
    float* out = (float*)d_out;

    float *h_base, *s_base, *p_base;
    __nv_bfloat16 *yh_base, *yl_base;
    cudaGetSymbolAddress((void**)&h_base, g_h);
    cudaGetSymbolAddress((void**)&s_base, g_S);
    cudaGetSymbolAddress((void**)&p_base, g_part);
    cudaGetSymbolAddress((void**)&yh_base, g_Yth);
    cudaGetSymbolAddress((void**)&yl_base, g_Ytl);

    cudaFuncSetAttribute(gemm_pipe_kernel,
                         cudaFuncAttributeMaxDynamicSharedMemorySize, 2 * STAGE_BYTES);

    for (int l = 0; l < N_LAYERS; l++) {
        const float* hc = (l == 0) ? node_embed : (h_base + (size_t)(l - 1) * NH);
        float* hn = h_base + (size_t)l * NH;
        compute_ys_kernel<<<dim3(64, 9), 256>>>(hc, w_self, w_rel, l, yh_base, yl_base, s_base);
        gemm_pipe_kernel<<<dim3(32, N_REL), 128, 2 * STAGE_BYTES>>>(
            rel_adj, yh_base, yl_base, p_base);
        finish_kernel<<<NH / 256, 256>>>(s_base, p_base, hn);
    }

    gather_kernel<<<2048, 64>>>(h_base + NH, keyword_ids, out);
}

// round 13
// speedup vs baseline: 1.6509x; 1.6509x over previous
#include <cuda_runtime.h>
#include <cuda_fp16.h>
#include <cstdint>

#define N_NODES 4096
#define HIDDEN  64
#define N_REL   8
#define N_LAYERS 2
#define NH (N_NODES * HIDDEN)

// ---------------------------------------------------------------- helpers
__device__ __forceinline__ uint32_t smem_u32(const void* p) {
    uint32_t a;
    asm("{ .reg .u64 t; cvta.to.shared.u64 t, %1; cvt.u32.u64 %0, t; }" : "=r"(a) : "l"(p));
    return a;
}

// pack two floats into f16x2 (f_even -> low half)
#define CVT_F16X2(d, f_even, f_odd) \
    asm("cvt.rn.f16x2.f32 %0, %1, %2;" : "=r"(d) : "f"(f_odd), "f"(f_even))

// unpack f16x2 -> two floats
#define UNPACK_F16X2(fe, fo, h2) \
    asm("{ .reg .f16 lo, hi; mov.b32 {lo, hi}, %2; cvt.f32.f16 %0, lo; cvt.f32.f16 %1, hi; }" \
        : "=f"(fe), "=f"(fo) : "r"(h2))

#define LDSM4(r, addr) \
    asm volatile("ldmatrix.sync.aligned.m8n8.x4.shared.b16 {%0,%1,%2,%3}, [%4];" \
        : "=r"((r)[0]), "=r"((r)[1]), "=r"((r)[2]), "=r"((r)[3]) : "r"(addr))

#define LDS64F(e, o, addr) \
    asm volatile("ld.shared.v2.f32 {%0,%1}, [%2];" : "=f"(e), "=f"(o) : "r"(addr))

#define MMAF16(c, a, b0, b1) \
    asm volatile("mma.sync.aligned.m16n8k16.row.col.f32.f16.f16.f32 " \
        "{%0,%1,%2,%3}, {%4,%5,%6,%7}, {%8,%9}, {%0,%1,%2,%3};" \
        : "+f"((c)[0]), "+f"((c)[1]), "+f"((c)[2]), "+f"((c)[3]) \
        : "r"((a)[0]), "r"((a)[1]), "r"((a)[2]), "r"((a)[3]), "r"(b0), "r"(b1))

#define LDGSTS16(dst, src) \
    asm volatile("cp.async.cg.shared.global [%0], [%1], 16;" :: "r"(dst), "l"(src))
#define CP_COMMIT() asm volatile("cp.async.commit_group;" ::: "memory")
#define CP_WAIT1() asm volatile("cp.async.wait_group 1;" ::: "memory")
#define CP_WAIT0() asm volatile("cp.async.wait_group 0;" ::: "memory")

// ---------------------------------------------------------------- scratch
__device__ float g_h[2][NH];                              // g_h[l] = output of layer l
__device__ float g_S[NH];
__device__ float g_part[N_REL][NH];
__device__ __half g_Yq[N_REL][HIDDEN][N_NODES];           // Y^T single fp16 [r][e][m]

// ---------------------------------------------------------------- Y / S
__global__ void __launch_bounds__(256) compute_ys_kernel(
    const float* __restrict__ h,
    const float* __restrict__ w_self,
    const float* __restrict__ w_rel,
    int layer,
    __half* __restrict__ Yq,
    float* __restrict__ S)
{
    __shared__ float sbuf[8448];
    float* Ws = sbuf;
    float* Hs = sbuf + 4096;
    float* Os = sbuf + 4096;

    int m0 = blockIdx.x * 64;
    int wi = blockIdx.y;
    const float* W = (wi < N_REL)
        ? (w_rel + ((size_t)layer * N_REL + wi) * HIDDEN * HIDDEN)
        : (w_self + (size_t)layer * HIDDEN * HIDDEN);

    int tid = threadIdx.x;
    const float4* Wg = (const float4*)W;
    const float4* Hg = (const float4*)(h + (size_t)m0 * HIDDEN);
    for (int i = tid; i < 1024; i += 256) {
        ((float4*)Ws)[i] = Wg[i];
        ((float4*)Hs)[i] = Hg[i];
    }
    __syncthreads();

    int tx = tid & 15, ty = tid >> 4;
    int e0 = tx * 4;
    float4 acc[4];
    #pragma unroll
    for (int mi = 0; mi < 4; mi++) {
        int m = ty * 4 + mi;
        float4 a = make_float4(0.f, 0.f, 0.f, 0.f);
        #pragma unroll
        for (int d = 0; d < HIDDEN; d++) {
            float hv = Hs[m * HIDDEN + d];
            float4 wv = *(const float4*)&Ws[d * HIDDEN + e0];
            a.x = fmaf(hv, wv.x, a.x);
            a.y = fmaf(hv, wv.y, a.y);
            a.z = fmaf(hv, wv.z, a.z);
            a.w = fmaf(hv, wv.w, a.w);
        }
        acc[mi] = a;
    }

    if (wi == N_REL) {
        #pragma unroll
        for (int mi = 0; mi < 4; mi++)
            *(float4*)&S[(size_t)(m0 + ty * 4 + mi) * HIDDEN + e0] = acc[mi];
        return;
    }

    __syncthreads();
    #pragma unroll
    for (int mi = 0; mi < 4; mi++)
        *(float4*)&Os[(ty * 4 + mi) * 68 + e0] = acc[mi];
    __syncthreads();

    int e   = tid >> 2;
    int seg = tid & 3;
    float v[16];
    #pragma unroll
    for (int i = 0; i < 16; i++)
        v[i] = Os[(seg * 16 + i) * 68 + e];

    uint32_t qw[8];
    #pragma unroll
    for (int j = 0; j < 8; j++)
        CVT_F16X2(qw[j], v[2 * j], v[2 * j + 1]);

    size_t off = ((size_t)wi * HIDDEN + e) * N_NODES + m0 + seg * 16;
    *(uint4*)(Yq + off)     = make_uint4(qw[0], qw[1], qw[2], qw[3]);
    *(uint4*)(Yq + off + 8) = make_uint4(qw[4], qw[5], qw[6], qw[7]);
}

// ---------------------------------------------------------------- pipelined tensor GEMM
// CTA 128(M) x 64(N), 4 warps, warp tile 32x64, KC=64, 2-stage cp.async.
// A fp32 in smem (288B rows, row&1 chunk-XOR); split to fp16 hi/lo limbs in
// regs (combined err ~2^-24). B = Y^T single fp16 (128B rows, row&7 XOR).
// 2 MMA terms per k16: ah*y + al*y.
// Stage: A @0 (128*288 = 36864 B), B @36864 (8192 B) = 45056 B.
#define KC 64
#define A_STRIDE 288
#define B_OFF 36864
#define STAGE_BYTES 45056

__device__ __forceinline__ void load_stage(
    uint32_t sbase, int stage, int mt, int tid,
    const float* Ag, const __half* Bg)
{
    const uint32_t st = sbase + stage * STAGE_BYTES;
    // A: 128 rows x 64 fp32 = 2048 16B-chunks; 16 per thread
    #pragma unroll
    for (int i = 0; i < 16; i++) {
        int c = tid + i * 128;
        int row = c >> 4, ch = c & 15;
        uint32_t dst = st + row * A_STRIDE + (((uint32_t)(ch ^ (row & 1))) << 4);
        const float* src = Ag + (size_t)row * N_NODES + mt + ch * 4;
        LDGSTS16(dst, src);
    }
    // B: 64 rows x 64 fp16 (128B rows) = 512 chunks; 4 per thread
    #pragma unroll
    for (int i = 0; i < 4; i++) {
        int c = tid + i * 128;
        int row = c >> 3, ch = c & 7;
        uint32_t dst = st + B_OFF + row * 128 + (((uint32_t)(ch ^ (row & 7))) << 4);
        size_t src = (size_t)row * N_NODES + mt + ch * 8;
        LDGSTS16(dst, Bg + src);
    }
}

__global__ void __launch_bounds__(128, 2) gemm_pipe_kernel(
    const float* __restrict__ adj,
    const __half* __restrict__ Yq,
    float* __restrict__ part)
{
    extern __shared__ __align__(16) char smem[];
    const int tid  = threadIdx.x;
    const int lane = tid & 31;
    const int warp_m = tid >> 5;        // 4 m-groups of 32; warp covers all 64 N
    const int n0 = blockIdx.x * 128;
    const int r  = blockIdx.y;
    const uint32_t sbase = smem_u32(smem);

    const float* Ag = adj + ((size_t)r << 24) + (size_t)(n0) * N_NODES;
    const __half* Bg = (const __half*)Yq + (size_t)r * HIDDEN * N_NODES;

    const int a_g = lane >> 2;
    const int a_t2 = (lane & 3) * 2;
    const int b_row_l = (lane >> 4) * 8 + (lane & 7);
    const int b_csel  = (lane >> 3) & 1;

    float c[2][8][4];
    #pragma unroll
    for (int i = 0; i < 2; i++)
        #pragma unroll
        for (int j = 0; j < 8; j++)
            #pragma unroll
            for (int k = 0; k < 4; k++) c[i][j][k] = 0.f;

    load_stage(sbase, 0, 0, tid, Ag, Bg);
    CP_COMMIT();

    #pragma unroll 1
    for (int it = 0; it < N_NODES / KC; ++it) {
        const int buf = it & 1;
        if (it < N_NODES / KC - 1) {
            load_stage(sbase, buf ^ 1, (it + 1) * KC, tid, Ag, Bg);
            CP_COMMIT();
            CP_WAIT1();
        } else {
            CP_WAIT0();
        }
        __syncthreads();

        const uint32_t st = sbase + buf * STAGE_BYTES;
        #pragma unroll
        for (int ks = 0; ks < 4; ks++) {
            // ---- B fragments (single fp16), 4 quads cover all 64 N ----
            uint32_t bq[4][4];
            #pragma unroll
            for (int p = 0; p < 4; p++) {
                int brow = p * 16 + b_row_l;
                uint32_t boff = brow * 128 +
                    (((uint32_t)((ks * 2 + b_csel) ^ (brow & 7))) << 4);
                LDSM4(bq[p], st + B_OFF + boff);
            }
            // ---- A fragments: LDS.64 fp32 pairs -> fp16 hi/lo limb split ----
            #pragma unroll
            for (int mi = 0; mi < 2; mi++) {
                uint32_t ah[4], al[4];
                #pragma unroll
                for (int j = 0; j < 4; j++) {
                    int row = warp_m * 32 + mi * 16 + a_g + (j & 1) * 8;
                    int k   = ks * 16 + ((j >> 1) << 3) + a_t2;
                    uint32_t addr = st + row * A_STRIDE +
                        (((uint32_t)((k >> 2) ^ (row & 1))) << 4) + (k & 3) * 4;
                    float e, o;
                    LDS64F(e, o, addr);
                    uint32_t hq;
                    CVT_F16X2(hq, e, o);
                    ah[j] = hq;
                    float fe, fo;
                    UNPACK_F16X2(fe, fo, hq);
                    float re = e - fe;
                    float ro = o - fo;
                    CVT_F16X2(al[j], re, ro);
                }
                #pragma unroll
                for (int p = 0; p < 4; p++) {
                    #pragma unroll
                    for (int q = 0; q < 2; q++) {
                        const int nf = p * 2 + q;
                        MMAF16(c[mi][nf], ah, bq[p][q * 2], bq[p][q * 2 + 1]);
                        MMAF16(c[mi][nf], al, bq[p][q * 2], bq[p][q * 2 + 1]);
                    }
                }
            }
        }
        __syncthreads();
    }

    // epilogue
    float* P = part + (size_t)r * NH;
    #pragma unroll
    for (int mi = 0; mi < 2; mi++) {
        const int rbase = n0 + warp_m * 32 + mi * 16 + (lane >> 2);
        #pragma unroll
        for (int nf = 0; nf < 8; nf++) {
            const int cbase = nf * 8 + (lane & 3) * 2;
            *(float2*)&P[(size_t)rbase * HIDDEN + cbase] =
                make_float2(c[mi][nf][0], c[mi][nf][1]);
            *(float2*)&P[(size_t)(rbase + 8) * HIDDEN + cbase] =
                make_float2(c[mi][nf][2], c[mi][nf][3]);
        }
    }
}

// ---------------------------------------------------------------- finish
__global__ void finish_kernel(const float* __restrict__ S,
                              const float* __restrict__ part,
                              float* __restrict__ hn)
{
    int i = blockIdx.x * blockDim.x + threadIdx.x;
    if (i < NH) {
        float v = S[i];
        #pragma unroll
        for (int r = 0; r < N_REL; r++) v += part[(size_t)r * NH + i];
        hn[i] = fmaxf(v, 0.f);
    }
}

// ---------------------------------------------------------------- gather
__global__ void gather_kernel(const float* __restrict__ h,
                              const int* __restrict__ ids,
                              float* __restrict__ out)
{
    int k = blockIdx.x;
    int e = threadIdx.x;
    int id = ids[k];
    float v = (id < N_NODES) ? h[(size_t)id * HIDDEN + e] : 0.f;
    out[(size_t)k * HIDDEN + e] = v;
}

// ----------------------------------------------------------------
extern "C" void kernel_launch(void* const* d_in, const int* in_sizes, int n_in,
                              void* d_out, int out_size)
{
    const float* node_embed  = (const float*)d_in[0];
    const float* w_self      = (const float*)d_in[1];
    const float* w_rel       = (const float*)d_in[2];
    const float* rel_adj     = (const float*)d_in[3];
    const int*   keyword_ids = (const int*)d_in[4];
    float* out = (float*)d_out;

    float *h_base, *s_base, *p_base;
    __half *yq_base;
    cudaGetSymbolAddress((void**)&h_base, g_h);
    cudaGetSymbolAddress((void**)&s_base, g_S);
    cudaGetSymbolAddress((void**)&p_base, g_part);
    cudaGetSymbolAddress((void**)&yq_base, g_Yq);

    cudaFuncSetAttribute(gemm_pipe_kernel,
                         cudaFuncAttributeMaxDynamicSharedMemorySize, 2 * STAGE_BYTES);

    for (int l = 0; l < N_LAYERS; l++) {
        const float* hc = (l == 0) ? node_embed : (h_base + (size_t)(l - 1) * NH);
        float* hn = h_base + (size_t)l * NH;
        compute_ys_kernel<<<dim3(64, 9), 256>>>(hc, w_self, w_rel, l, yq_base, s_base);
        gemm_pipe_kernel<<<dim3(32, N_REL), 128, 2 * STAGE_BYTES>>>(
            rel_adj, yq_base, p_base);
        finish_kernel<<<NH / 256, 256>>>(s_base, p_base, hn);
    }

    gather_kernel<<<2048, 64>>>(h_base + NH, keyword_ids, out);
}

// round 14
// speedup vs baseline: 1.9813x; 1.2001x over previous
#include <cuda_runtime.h>
#include <cuda_fp16.h>
#include <cstdint>

#define N_NODES 4096
#define HIDDEN  64
#define N_REL   8
#define N_LAYERS 2
#define NH (N_NODES * HIDDEN)

// ---------------------------------------------------------------- helpers
__device__ __forceinline__ uint32_t smem_u32(const void* p) {
    uint32_t a;
    asm("{ .reg .u64 t; cvta.to.shared.u64 t, %1; cvt.u32.u64 %0, t; }" : "=r"(a) : "l"(p));
    return a;
}

// pack two floats into f16x2 (f_even -> low half)
#define CVT_F16X2(d, f_even, f_odd) \
    asm("cvt.rn.f16x2.f32 %0, %1, %2;" : "=r"(d) : "f"(f_odd), "f"(f_even))

#define LDSM4(r, addr) \
    asm volatile("ldmatrix.sync.aligned.m8n8.x4.shared.b16 {%0,%1,%2,%3}, [%4];" \
        : "=r"((r)[0]), "=r"((r)[1]), "=r"((r)[2]), "=r"((r)[3]) : "r"(addr))

#define LDS64F(e, o, addr) \
    asm volatile("ld.shared.v2.f32 {%0,%1}, [%2];" : "=f"(e), "=f"(o) : "r"(addr))

#define MMAF16(c, a, b0, b1) \
    asm volatile("mma.sync.aligned.m16n8k16.row.col.f32.f16.f16.f32 " \
        "{%0,%1,%2,%3}, {%4,%5,%6,%7}, {%8,%9}, {%0,%1,%2,%3};" \
        : "+f"((c)[0]), "+f"((c)[1]), "+f"((c)[2]), "+f"((c)[3]) \
        : "r"((a)[0]), "r"((a)[1]), "r"((a)[2]), "r"((a)[3]), "r"(b0), "r"(b1))

#define LDGSTS16(dst, src) \
    asm volatile("cp.async.cg.shared.global [%0], [%1], 16;" :: "r"(dst), "l"(src))
#define CP_COMMIT() asm volatile("cp.async.commit_group;" ::: "memory")
#define CP_WAIT1() asm volatile("cp.async.wait_group 1;" ::: "memory")
#define CP_WAIT0() asm volatile("cp.async.wait_group 0;" ::: "memory")

// ---------------------------------------------------------------- scratch
__device__ float g_h[2][NH];                              // g_h[l] = output of layer l
__device__ float g_S[NH];
__device__ float g_part[N_REL][NH];
__device__ __half g_Yq[N_REL][HIDDEN][N_NODES];           // Y^T single fp16 [r][e][m]

// ---------------------------------------------------------------- Y / S
__global__ void __launch_bounds__(256) compute_ys_kernel(
    const float* __restrict__ h,
    const float* __restrict__ w_self,
    const float* __restrict__ w_rel,
    int layer,
    __half* __restrict__ Yq,
    float* __restrict__ S)
{
    __shared__ float sbuf[8448];
    float* Ws = sbuf;
    float* Hs = sbuf + 4096;
    float* Os = sbuf + 4096;

    int m0 = blockIdx.x * 64;
    int wi = blockIdx.y;
    const float* W = (wi < N_REL)
        ? (w_rel + ((size_t)layer * N_REL + wi) * HIDDEN * HIDDEN)
        : (w_self + (size_t)layer * HIDDEN * HIDDEN);

    int tid = threadIdx.x;
    const float4* Wg = (const float4*)W;
    const float4* Hg = (const float4*)(h + (size_t)m0 * HIDDEN);
    for (int i = tid; i < 1024; i += 256) {
        ((float4*)Ws)[i] = Wg[i];
        ((float4*)Hs)[i] = Hg[i];
    }
    __syncthreads();

    int tx = tid & 15, ty = tid >> 4;
    int e0 = tx * 4;
    float4 acc[4];
    #pragma unroll
    for (int mi = 0; mi < 4; mi++) {
        int m = ty * 4 + mi;
        float4 a = make_float4(0.f, 0.f, 0.f, 0.f);
        #pragma unroll
        for (int d = 0; d < HIDDEN; d++) {
            float hv = Hs[m * HIDDEN + d];
            float4 wv = *(const float4*)&Ws[d * HIDDEN + e0];
            a.x = fmaf(hv, wv.x, a.x);
            a.y = fmaf(hv, wv.y, a.y);
            a.z = fmaf(hv, wv.z, a.z);
            a.w = fmaf(hv, wv.w, a.w);
        }
        acc[mi] = a;
    }

    if (wi == N_REL) {
        #pragma unroll
        for (int mi = 0; mi < 4; mi++)
            *(float4*)&S[(size_t)(m0 + ty * 4 + mi) * HIDDEN + e0] = acc[mi];
        return;
    }

    __syncthreads();
    #pragma unroll
    for (int mi = 0; mi < 4; mi++)
        *(float4*)&Os[(ty * 4 + mi) * 68 + e0] = acc[mi];
    __syncthreads();

    int e   = tid >> 2;
    int seg = tid & 3;
    float v[16];
    #pragma unroll
    for (int i = 0; i < 16; i++)
        v[i] = Os[(seg * 16 + i) * 68 + e];

    uint32_t qw[8];
    #pragma unroll
    for (int j = 0; j < 8; j++)
        CVT_F16X2(qw[j], v[2 * j], v[2 * j + 1]);

    size_t off = ((size_t)wi * HIDDEN + e) * N_NODES + m0 + seg * 16;
    *(uint4*)(Yq + off)     = make_uint4(qw[0], qw[1], qw[2], qw[3]);
    *(uint4*)(Yq + off + 8) = make_uint4(qw[4], qw[5], qw[6], qw[7]);
}

// ---------------------------------------------------------------- pipelined tensor GEMM
// CTA 128(M) x 64(N), 4 warps, warp tile 32x64, KC=64, 2-stage cp.async.
// A fp32 in smem (288B rows, row&1 chunk-XOR) -> single fp16 fragments in regs.
// B = Y^T single fp16 (128B rows, row&7 XOR). ONE MMA term per k16.
// Stage: A @0 (128*288 = 36864 B), B @36864 (8192 B) = 45056 B.
#define KC 64
#define A_STRIDE 288
#define B_OFF 36864
#define STAGE_BYTES 45056

__device__ __forceinline__ void load_stage(
    uint32_t sbase, int stage, int mt, int tid,
    const float* Ag, const __half* Bg)
{
    const uint32_t st = sbase + stage * STAGE_BYTES;
    // A: 128 rows x 64 fp32 = 2048 16B-chunks; 16 per thread
    #pragma unroll
    for (int i = 0; i < 16; i++) {
        int c = tid + i * 128;
        int row = c >> 4, ch = c & 15;
        uint32_t dst = st + row * A_STRIDE + (((uint32_t)(ch ^ (row & 1))) << 4);
        const float* src = Ag + (size_t)row * N_NODES + mt + ch * 4;
        LDGSTS16(dst, src);
    }
    // B: 64 rows x 64 fp16 (128B rows) = 512 chunks; 4 per thread
    #pragma unroll
    for (int i = 0; i < 4; i++) {
        int c = tid + i * 128;
        int row = c >> 3, ch = c & 7;
        uint32_t dst = st + B_OFF + row * 128 + (((uint32_t)(ch ^ (row & 7))) << 4);
        size_t src = (size_t)row * N_NODES + mt + ch * 8;
        LDGSTS16(dst, Bg + src);
    }
}

__global__ void __launch_bounds__(128, 2) gemm_pipe_kernel(
    const float* __restrict__ adj,
    const __half* __restrict__ Yq,
    float* __restrict__ part)
{
    extern __shared__ __align__(16) char smem[];
    const int tid  = threadIdx.x;
    const int lane = tid & 31;
    const int warp_m = tid >> 5;        // 4 m-groups of 32; warp covers all 64 N
    const int n0 = blockIdx.x * 128;
    const int r  = blockIdx.y;
    const uint32_t sbase = smem_u32(smem);

    const float* Ag = adj + ((size_t)r << 24) + (size_t)(n0) * N_NODES;
    const __half* Bg = (const __half*)Yq + (size_t)r * HIDDEN * N_NODES;

    const int a_g = lane >> 2;
    const int a_t2 = (lane & 3) * 2;
    const int b_row_l = (lane >> 4) * 8 + (lane & 7);
    const int b_csel  = (lane >> 3) & 1;

    float c[2][8][4];
    #pragma unroll
    for (int i = 0; i < 2; i++)
        #pragma unroll
        for (int j = 0; j < 8; j++)
            #pragma unroll
            for (int k = 0; k < 4; k++) c[i][j][k] = 0.f;

    load_stage(sbase, 0, 0, tid, Ag, Bg);
    CP_COMMIT();

    #pragma unroll 1
    for (int it = 0; it < N_NODES / KC; ++it) {
        const int buf = it & 1;
        if (it < N_NODES / KC - 1) {
            load_stage(sbase, buf ^ 1, (it + 1) * KC, tid, Ag, Bg);
            CP_COMMIT();
            CP_WAIT1();
        } else {
            CP_WAIT0();
        }
        __syncthreads();

        const uint32_t st = sbase + buf * STAGE_BYTES;
        #pragma unroll
        for (int ks = 0; ks < 4; ks++) {
            // ---- B fragments (single fp16), 4 quads cover all 64 N ----
            uint32_t bq[4][4];
            #pragma unroll
            for (int p = 0; p < 4; p++) {
                int brow = p * 16 + b_row_l;
                uint32_t boff = brow * 128 +
                    (((uint32_t)((ks * 2 + b_csel) ^ (brow & 7))) << 4);
                LDSM4(bq[p], st + B_OFF + boff);
            }
            // ---- A fragments: LDS.64 fp32 pairs -> single fp16 ----
            #pragma unroll
            for (int mi = 0; mi < 2; mi++) {
                uint32_t ah[4];
                #pragma unroll
                for (int j = 0; j < 4; j++) {
                    int row = warp_m * 32 + mi * 16 + a_g + (j & 1) * 8;
                    int k   = ks * 16 + ((j >> 1) << 3) + a_t2;
                    uint32_t addr = st + row * A_STRIDE +
                        (((uint32_t)((k >> 2) ^ (row & 1))) << 4) + (k & 3) * 4;
                    float e, o;
                    LDS64F(e, o, addr);
                    CVT_F16X2(ah[j], e, o);
                }
                #pragma unroll
                for (int p = 0; p < 4; p++) {
                    #pragma unroll
                    for (int q = 0; q < 2; q++) {
                        const int nf = p * 2 + q;
                        MMAF16(c[mi][nf], ah, bq[p][q * 2], bq[p][q * 2 + 1]);
                    }
                }
            }
        }
        __syncthreads();
    }

    // epilogue
    float* P = part + (size_t)r * NH;
    #pragma unroll
    for (int mi = 0; mi < 2; mi++) {
        const int rbase = n0 + warp_m * 32 + mi * 16 + (lane >> 2);
        #pragma unroll
        for (int nf = 0; nf < 8; nf++) {
            const int cbase = nf * 8 + (lane & 3) * 2;
            *(float2*)&P[(size_t)rbase * HIDDEN + cbase] =
                make_float2(c[mi][nf][0], c[mi][nf][1]);
            *(float2*)&P[(size_t)(rbase + 8) * HIDDEN + cbase] =
                make_float2(c[mi][nf][2], c[mi][nf][3]);
        }
    }
}

// ---------------------------------------------------------------- finish
__global__ void finish_kernel(const float* __restrict__ S,
                              const float* __restrict__ part,
                              float* __restrict__ hn)
{
    int i = blockIdx.x * blockDim.x + threadIdx.x;
    if (i < NH) {
        float v = S[i];
        #pragma unroll
        for (int r = 0; r < N_REL; r++) v += part[(size_t)r * NH + i];
        hn[i] = fmaxf(v, 0.f);
    }
}

// ---------------------------------------------------------------- gather
__global__ void gather_kernel(const float* __restrict__ h,
                              const int* __restrict__ ids,
                              float* __restrict__ out)
{
    int k = blockIdx.x;
    int e = threadIdx.x;
    int id = ids[k];
    float v = (id < N_NODES) ? h[(size_t)id * HIDDEN + e] : 0.f;
    out[(size_t)k * HIDDEN + e] = v;
}

// ----------------------------------------------------------------
extern "C" void kernel_launch(void* const* d_in, const int* in_sizes, int n_in,
                              void* d_out, int out_size)
{
    const float* node_embed  = (const float*)d_in[0];
    const float* w_self      = (const float*)d_in[1];
    const float* w_rel       = (const float*)d_in[2];
    const float* rel_adj     = (const float*)d_in[3];
    const int*   keyword_ids = (const int*)d_in[4];
    float* out = (float*)d_out;

    float *h_base, *s_base, *p_base;
    __half *yq_base;
    cudaGetSymbolAddress((void**)&h_base, g_h);
    cudaGetSymbolAddress((void**)&s_base, g_S);
    cudaGetSymbolAddress((void**)&p_base, g_part);
    cudaGetSymbolAddress((void**)&yq_base, g_Yq);

    cudaFuncSetAttribute(gemm_pipe_kernel,
                         cudaFuncAttributeMaxDynamicSharedMemorySize, 2 * STAGE_BYTES);

    for (int l = 0; l < N_LAYERS; l++) {
        const float* hc = (l == 0) ? node_embed : (h_base + (size_t)(l - 1) * NH);
        float* hn = h_base + (size_t)l * NH;
        compute_ys_kernel<<<dim3(64, 9), 256>>>(hc, w_self, w_rel, l, yq_base, s_base);
        gemm_pipe_kernel<<<dim3(32, N_REL), 128, 2 * STAGE_BYTES>>>(
            rel_adj, yq_base, p_base);
        finish_kernel<<<NH / 256, 256>>>(s_base, p_base, hn);
    }

    gather_kernel<<<2048, 64>>>(h_base + NH, keyword_ids, out);
}